// round 6
// baseline (speedup 1.0000x reference)
#include <cuda_runtime.h>
#include <cstdint>

// KDPointToPointLoss: loss[b] = (1/(3N)) * sum_n min_m ||s[b,:,n] - t[b,:,m]||^2
// B=8, C=3, N=M=4096.
//
// Dense exact fp32 is AT the FMA roofline (~22us). This version prunes pairs
// exactly: counting-sort targets+sources by Morton cell, 64-target chunks with
// AABBs; per source point scan only chunks whose AABB lower bound beats the
// current best. Pruning via AABB lb <= member d2 is provably exact -> result
// identical to dense. Output order canonicalized via original source indices
// -> deterministic despite atomic scatter order.

#define BATCH 8
#define NPTS  4096
#define MPTS  4096
#define CELLS 4096              // 16^3 Morton grid over [-5,5], cell 0.625
#define NCHUNKS 64              // 64 targets per chunk
#define SB    64                // search block threads (1 sorted point each)

__device__ float4 g_tsort[BATCH * MPTS];   // sorted targets (x,y,z,|t|^2)
__device__ float4 g_ssort[BATCH * NPTS];   // sorted sources (x,y,z,|s|^2)
__device__ int    g_sidx [BATCH * NPTS];   // original index of sorted source
__device__ float4 g_alo  [BATCH * NCHUNKS];// chunk AABB lo (w unused)
__device__ float4 g_ahi  [BATCH * NCHUNKS];// chunk AABB hi
__device__ float  g_d2   [BATCH * NPTS];   // min d2 per (b, original n)
__device__ float  g_s1   [BATCH * 8];      // reduce stage1 partials

__device__ __forceinline__ int spread3(int v) {
    return (v & 1) | ((v & 2) << 2) | ((v & 4) << 4) | ((v & 8) << 6);
}
__device__ __forceinline__ int cell_of(float x, float y, float z) {
    int cx = min(15, max(0, (int)((x + 5.0f) * 1.6f)));
    int cy = min(15, max(0, (int)((y + 5.0f) * 1.6f)));
    int cz = min(15, max(0, (int)((z + 5.0f) * 1.6f)));
    return spread3(cx) | (spread3(cy) << 1) | (spread3(cz) << 2);
}

// Exclusive scan of hist[CELLS] in place. 512 threads, 8 cells each.
__device__ void block_scan(int* hist, int* sc, int tid) {
    int base = tid * 8;
    int v[8], s = 0;
#pragma unroll
    for (int k = 0; k < 8; k++) v[k] = hist[base + k];
#pragma unroll
    for (int k = 0; k < 8; k++) { int t = v[k]; v[k] = s; s += t; }
    sc[tid] = s;
    __syncthreads();
    for (int o = 1; o < 512; o <<= 1) {
        int t = (tid >= o) ? sc[tid - o] : 0;
        __syncthreads();
        sc[tid] += t;
        __syncthreads();
    }
    int excl = sc[tid] - s;
#pragma unroll
    for (int k = 0; k < 8; k++) hist[base + k] = v[k] + excl;
    __syncthreads();
}

__global__ __launch_bounds__(512) void build_kernel(
    const float* __restrict__ src, const float* __restrict__ tgt) {
    __shared__ int hist[CELLS];
    __shared__ int sc[512];
    const int b = blockIdx.x, tid = threadIdx.x;
    const float* tb = tgt + (size_t)b * 3 * MPTS;
    const float* sb = src + (size_t)b * 3 * NPTS;

    // ---- targets: count, scan, scatter ----
    for (int i = tid; i < CELLS; i += 512) hist[i] = 0;
    __syncthreads();
    for (int i = tid; i < MPTS; i += 512)
        atomicAdd(&hist[cell_of(tb[i], tb[MPTS + i], tb[2 * MPTS + i])], 1);
    __syncthreads();
    block_scan(hist, sc, tid);
    for (int i = tid; i < MPTS; i += 512) {
        float x = tb[i], y = tb[MPTS + i], z = tb[2 * MPTS + i];
        int pos = atomicAdd(&hist[cell_of(x, y, z)], 1);
        g_tsort[b * MPTS + pos] =
            make_float4(x, y, z, fmaf(x, x, fmaf(y, y, z * z)));
    }
    __syncthreads();  // g_tsort visible block-wide

    // ---- chunk AABBs: one warp per chunk ----
    {
        int wid = tid >> 5, lane = tid & 31;
        for (int c = wid; c < NCHUNKS; c += 16) {
            float4 a = g_tsort[b * MPTS + c * 64 + lane];
            float4 d = g_tsort[b * MPTS + c * 64 + 32 + lane];
            float lx = fminf(a.x, d.x), ly = fminf(a.y, d.y), lz = fminf(a.z, d.z);
            float hx = fmaxf(a.x, d.x), hy = fmaxf(a.y, d.y), hz = fmaxf(a.z, d.z);
#pragma unroll
            for (int o = 16; o > 0; o >>= 1) {
                lx = fminf(lx, __shfl_xor_sync(0xFFFFFFFFu, lx, o));
                ly = fminf(ly, __shfl_xor_sync(0xFFFFFFFFu, ly, o));
                lz = fminf(lz, __shfl_xor_sync(0xFFFFFFFFu, lz, o));
                hx = fmaxf(hx, __shfl_xor_sync(0xFFFFFFFFu, hx, o));
                hy = fmaxf(hy, __shfl_xor_sync(0xFFFFFFFFu, hy, o));
                hz = fmaxf(hz, __shfl_xor_sync(0xFFFFFFFFu, hz, o));
            }
            if (lane == 0) {
                g_alo[b * NCHUNKS + c] = make_float4(lx, ly, lz, 0.0f);
                g_ahi[b * NCHUNKS + c] = make_float4(hx, hy, hz, 0.0f);
            }
        }
    }
    __syncthreads();

    // ---- sources: count, scan, scatter (with original index) ----
    for (int i = tid; i < CELLS; i += 512) hist[i] = 0;
    __syncthreads();
    for (int i = tid; i < NPTS; i += 512)
        atomicAdd(&hist[cell_of(sb[i], sb[NPTS + i], sb[2 * NPTS + i])], 1);
    __syncthreads();
    block_scan(hist, sc, tid);
    for (int i = tid; i < NPTS; i += 512) {
        float x = sb[i], y = sb[NPTS + i], z = sb[2 * NPTS + i];
        int pos = atomicAdd(&hist[cell_of(x, y, z)], 1);
        g_ssort[b * NPTS + pos] =
            make_float4(x, y, z, fmaf(x, x, fmaf(y, y, z * z)));
        g_sidx[b * NPTS + pos] = i;
    }
}

__global__ __launch_bounds__(SB) void search_kernel() {
    __shared__ float4 alo[NCHUNKS], ahi[NCHUNKS];
    __shared__ float lbs[NCHUNKS * SB];
    const int b = blockIdx.y, tid = threadIdx.x;
    const int i = blockIdx.x * SB + tid;  // sorted source index

    if (tid < NCHUNKS) {
        alo[tid] = g_alo[b * NCHUNKS + tid];
        ahi[tid] = g_ahi[b * NCHUNKS + tid];
    }
    __syncthreads();

    float4 s = g_ssort[b * NPTS + i];
    const float cx = -2.0f * s.x, cy = -2.0f * s.y, cz = -2.0f * s.z;
    const float sw = s.w;

    // Pass 1: AABB lower bounds (true d2 lower bound per chunk).
    float bestLB = 3.4e38f;
    int cbest = 0;
#pragma unroll 4
    for (int c = 0; c < NCHUNKS; c++) {
        float4 lo = alo[c], hi = ahi[c];
        float dx = fmaxf(fmaxf(lo.x - s.x, s.x - hi.x), 0.0f);
        float dy = fmaxf(fmaxf(lo.y - s.y, s.y - hi.y), 0.0f);
        float dz = fmaxf(fmaxf(lo.z - s.z, s.z - hi.z), 0.0f);
        float lb = fmaf(dx, dx, fmaf(dy, dy, dz * dz));
        lbs[c * SB + tid] = lb;
        if (lb < bestLB) { bestLB = lb; cbest = c; }
    }

    const float4* tp = g_tsort + b * MPTS;
    float best_sc = 3.4e38f;  // score = |t|^2 - 2 s.t ; d2 = score + |s|^2

    // Tighten with the nearest chunk first.
    {
        const float4* p = tp + cbest * 64;
#pragma unroll 8
        for (int j = 0; j < 64; j++) {
            float4 t = p[j];
            float v = fmaf(cx, t.x, fmaf(cy, t.y, fmaf(cz, t.z, t.w)));
            best_sc = fminf(best_sc, v);
        }
    }

    // Pass 2: scan only chunks whose lb can beat current best (exact pruning).
    for (int c = 0; c < NCHUNKS; c++) {
        if (c != cbest && lbs[c * SB + tid] < best_sc + sw) {
            const float4* p = tp + c * 64;
#pragma unroll 8
            for (int j = 0; j < 64; j++) {
                float4 t = p[j];
                float v = fmaf(cx, t.x, fmaf(cy, t.y, fmaf(cz, t.z, t.w)));
                best_sc = fminf(best_sc, v);
            }
        }
    }

    // Write in ORIGINAL index order -> deterministic downstream sum.
    g_d2[b * NPTS + g_sidx[b * NPTS + i]] = best_sc + sw;
}

__global__ __launch_bounds__(256) void reduce1_kernel() {
    __shared__ float sh[256];
    const int sl = blockIdx.x, b = blockIdx.y;
    const int i0 = sl * (NPTS / 8);
    float s = 0.0f;
    for (int i = threadIdx.x; i < NPTS / 8; i += 256)
        s += g_d2[b * NPTS + i0 + i];
    sh[threadIdx.x] = s;
    __syncthreads();
    for (int o = 128; o > 0; o >>= 1) {
        if (threadIdx.x < o) sh[threadIdx.x] += sh[threadIdx.x + o];
        __syncthreads();
    }
    if (threadIdx.x == 0) g_s1[b * 8 + sl] = sh[0];
}

__global__ void reduce2_kernel(float* __restrict__ out) {
    int b = threadIdx.x;
    if (b < BATCH) {
        float s = 0.0f;
#pragma unroll
        for (int t = 0; t < 8; t++) s += g_s1[b * 8 + t];
        out[b] = s * (1.0f / (3.0f * NPTS));
    }
}

extern "C" void kernel_launch(void* const* d_in, const int* in_sizes, int n_in,
                              void* d_out, int out_size) {
    const float* src = (const float*)d_in[0];  // [B,3,N]
    const float* tgt = (const float*)d_in[1];  // [B,3,M]
    float* out = (float*)d_out;                // [B]

    build_kernel<<<BATCH, 512>>>(src, tgt);
    search_kernel<<<dim3(NPTS / SB, BATCH), SB>>>();
    reduce1_kernel<<<dim3(8, BATCH), 256>>>();
    reduce2_kernel<<<1, 32>>>(out);
}

// round 7
// speedup vs baseline: 3.9797x; 3.9797x over previous
#include <cuda_runtime.h>
#include <cstdint>

// KDPointToPointLoss: loss[b] = (1/(3N)) * sum_n min_m ||s[b,:,n] - t[b,:,m]||^2
// B=8, C=3, N=M=4096 (fixed by dataset).
//
// Dense exact fp32. score(n,m) = |t_m|^2 - 2 s_n.t_m (monotone in d2).
// Targets in smem as two 16B interleaved words per pair -> 2x LDS.128 per j2.
// fma.rn.f32x2 inner loop, ILP=8 source points/thread (8 independent dep
// streams hide LDS + cross-pipe latency). Grid 32x4x8 = 1024 blocks.
// Single fused reduce kernel (counter-based last-block finish), deterministic.

#define BATCH 8
#define NPTS  4096
#define MPTS  4096

#define THREADS   128
#define ILP       8                       // source points per thread
#define SRC_PER_BLOCK (THREADS * ILP)     // 1024
#define SRC_CHUNKS (NPTS / SRC_PER_BLOCK) // 4
#define TSPLIT    32                      // target splits
#define TC        (MPTS / TSPLIT)         // 128 targets per block
#define TC2       (TC / 2)                // 64 packed pairs

#define RSLICES   8                       // point-slices per batch in reduce
#define RPTS      (NPTS / RSLICES)        // 512 points per reduce block

__device__ float g_part[TSPLIT * BATCH * NPTS];   // partial min d2 per (ts,b,n)
__device__ float g_s1[BATCH * RSLICES];           // per-slice sums
__device__ int   g_cnt[BATCH];                    // arrival counters (reset each run)

__device__ __forceinline__ unsigned long long ffma2(
    unsigned long long a, unsigned long long b, unsigned long long c) {
    unsigned long long d;
    asm("fma.rn.f32x2 %0, %1, %2, %3;" : "=l"(d) : "l"(a), "l"(b), "l"(c));
    return d;
}
__device__ __forceinline__ unsigned long long pack2(float lo, float hi) {
    unsigned long long r;
    asm("mov.b64 %0, {%1, %2};" : "=l"(r) : "f"(lo), "f"(hi));
    return r;
}
__device__ __forceinline__ void unpack2(unsigned long long v, float& lo, float& hi) {
    asm("mov.b64 {%0, %1}, %2;" : "=f"(lo), "=f"(hi) : "l"(v));
}

__global__ __launch_bounds__(THREADS) void nn_kernel(
    const float* __restrict__ src, const float* __restrict__ tgt) {
    // Interleaved: sxy[j2] = {packed x pair, packed y pair},
    //              szw[j2] = {packed z pair, packed |t|^2 pair} -> LDS.128.
    __shared__ ulonglong2 sxy[TC2], szw[TC2];

    const int ts   = blockIdx.x;               // target split
    const int src0 = blockIdx.y * SRC_PER_BLOCK;
    const int b    = blockIdx.z;
    const int tid  = threadIdx.x;
    const int tgt0 = ts * TC;

    // Cooperative packed load of this target chunk (TC2=64 < THREADS).
    const float2* tx = (const float2*)(tgt + (size_t)b * 3 * MPTS + 0 * MPTS + tgt0);
    const float2* ty = (const float2*)(tgt + (size_t)b * 3 * MPTS + 1 * MPTS + tgt0);
    const float2* tz = (const float2*)(tgt + (size_t)b * 3 * MPTS + 2 * MPTS + tgt0);
    if (tid < TC2) {
        int j2 = tid;
        float2 x = tx[j2];
        float2 y = ty[j2];
        float2 z = tz[j2];
        float w0 = fmaf(x.x, x.x, fmaf(y.x, y.x, z.x * z.x));
        float w1 = fmaf(x.y, x.y, fmaf(y.y, y.y, z.y * z.y));
        sxy[j2] = make_ulonglong2(pack2(x.x, x.y), pack2(y.x, y.y));
        szw[j2] = make_ulonglong2(pack2(z.x, z.y), pack2(w0, w1));
    }

    // Per-thread source points: packed duplicated coefficients (-2s, -2s).
    const float* sb = src + (size_t)b * 3 * NPTS;
    unsigned long long cx2[ILP], cy2[ILP], cz2[ILP];
    float s2[ILP], mnLo[ILP], mnHi[ILP];
#pragma unroll
    for (int p = 0; p < ILP; p++) {
        int n = src0 + p * THREADS + tid;
        float sx = sb[0 * NPTS + n];
        float sy = sb[1 * NPTS + n];
        float sz = sb[2 * NPTS + n];
        cx2[p] = pack2(-2.0f * sx, -2.0f * sx);
        cy2[p] = pack2(-2.0f * sy, -2.0f * sy);
        cz2[p] = pack2(-2.0f * sz, -2.0f * sz);
        s2[p]  = fmaf(sx, sx, fmaf(sy, sy, sz * sz));
        mnLo[p] = 1e30f;
        mnHi[p] = 1e30f;
    }
    __syncthreads();

    // Main loop: per j2 (2 targets): 2 LDS.128 + 8*(3 FFMA2 + 2 FMNMX)
    // = ~2.6 instr per point-target pair, 8 independent dep streams.
#pragma unroll 2
    for (int j2 = 0; j2 < TC2; j2++) {
        ulonglong2 vxy = sxy[j2];
        ulonglong2 vzw = szw[j2];
#pragma unroll
        for (int p = 0; p < ILP; p++) {
            unsigned long long acc = ffma2(cz2[p], vzw.x, vzw.y);
            acc = ffma2(cy2[p], vxy.y, acc);
            acc = ffma2(cx2[p], vxy.x, acc);
            float lo, hi;
            unpack2(acc, lo, hi);
            mnLo[p] = fminf(mnLo[p], lo);
            mnHi[p] = fminf(mnHi[p], hi);
        }
    }

    // Store partial d2 (add |s|^2 now so the reduce is pure min+sum).
    float* part = g_part + ((size_t)ts * BATCH + b) * NPTS;
#pragma unroll
    for (int p = 0; p < ILP; p++) {
        int n = src0 + p * THREADS + tid;
        part[n] = fminf(mnLo[p], mnHi[p]) + s2[p];
    }
}

// Fused reduce: grid = (RSLICES, BATCH). Each block mins the TSPLIT partials
// for its 512 points and block-sums into g_s1. The LAST arriving block of each
// batch (atomic counter) does the fixed-order 8-slice sum -> out[b], then
// resets the counter for graph replay. Deterministic: the final summation
// order is fixed regardless of which block performs it.
__global__ __launch_bounds__(256) void reduce_kernel(float* __restrict__ out) {
    __shared__ float sh[256];
    __shared__ int amLast;
    const int sl = blockIdx.x, b = blockIdx.y;
    const int i0 = sl * RPTS;
    float s = 0.0f;
    for (int i = threadIdx.x; i < RPTS; i += 256) {
        int n = i0 + i;
        float m = g_part[(size_t)b * NPTS + n];  // ts = 0
#pragma unroll
        for (int t = 1; t < TSPLIT; t++)
            m = fminf(m, g_part[((size_t)t * BATCH + b) * NPTS + n]);
        s += m;
    }
    sh[threadIdx.x] = s;
    __syncthreads();
    for (int o = 128; o > 0; o >>= 1) {
        if (threadIdx.x < o) sh[threadIdx.x] += sh[threadIdx.x + o];
        __syncthreads();
    }
    if (threadIdx.x == 0) {
        g_s1[b * RSLICES + sl] = sh[0];
        __threadfence();
        int prev = atomicAdd(&g_cnt[b], 1);
        amLast = (prev == RSLICES - 1);
    }
    __syncthreads();
    if (amLast && threadIdx.x == 0) {
        __threadfence();
        float tot = 0.0f;
#pragma unroll
        for (int t = 0; t < RSLICES; t++) tot += g_s1[b * RSLICES + t];
        out[b] = tot * (1.0f / (3.0f * NPTS));
        g_cnt[b] = 0;  // reset for next graph replay
    }
}

extern "C" void kernel_launch(void* const* d_in, const int* in_sizes, int n_in,
                              void* d_out, int out_size) {
    const float* src = (const float*)d_in[0];  // [B,3,N]
    const float* tgt = (const float*)d_in[1];  // [B,3,M]
    float* out = (float*)d_out;                // [B]

    dim3 grid(TSPLIT, SRC_CHUNKS, BATCH);      // 32 x 4 x 8 = 1024 blocks
    nn_kernel<<<grid, THREADS>>>(src, tgt);

    dim3 rgrid(RSLICES, BATCH);                // 8 x 8 = 64 blocks
    reduce_kernel<<<rgrid, 256>>>(out);
}